// round 1
// baseline (speedup 1.0000x reference)
#include <cuda_runtime.h>

// ---------------------------------------------------------------------------
// QNNClassifier: out[b] = fc_w * <Z0>(x[b]; q_params) + fc_b
//
// Algebraic reduction:
//   psi0 = kron(RY(x0)|0>, RY(x1)|0>) is REAL, so
//   ev   = psi0^T A psi0,  A = Re(U^H (Z(x)I) U)   (A real symmetric, batch-shared)
// and with double-angle identities:
//   ev   = (1, cos x0, sin x0)^T K (1, cos x1, sin x1)   (9 coefficients)
// fc_w folded into K, fc_b folded into K[0][0].
// ---------------------------------------------------------------------------

struct Cx { float re, im; };
__device__ __forceinline__ Cx cmul(Cx a, Cx b) {
    return { a.re * b.re - a.im * b.im, a.re * b.im + a.im * b.re };
}
__device__ __forceinline__ Cx cadd(Cx a, Cx b) { return { a.re + b.re, a.im + b.im }; }
__device__ __forceinline__ Cx cconj(Cx a)      { return { a.re, -a.im }; }

__device__ float g_K[9];   // k00 k01 k02 k10 k11 k12 k20 k21 k22

// --- prep: compute the 9 batch-shared coefficients from q_params/fc ---------
__global__ void qnn_prep_kernel(const float* __restrict__ qp,
                                const float* __restrict__ fc_w,
                                const float* __restrict__ fc_b) {
    if (threadIdx.x != 0 || blockIdx.x != 0) return;

    Cx U[4][4];
    #pragma unroll
    for (int i = 0; i < 4; i++)
        #pragma unroll
        for (int j = 0; j < 4; j++)
            U[i][j] = { (i == j) ? 1.f : 0.f, 0.f };

    for (int l = 0; l < 2; l++) {
        // Rot(phi, theta, omega) = RZ(omega) RY(theta) RZ(phi) for each wire
        Cx r[2][2][2];
        for (int w = 0; w < 2; w++) {
            float phi   = qp[(l * 2 + w) * 3 + 0];
            float theta = qp[(l * 2 + w) * 3 + 1];
            float omega = qp[(l * 2 + w) * 3 + 2];
            float c, s;
            __sincosf(0.5f * theta, &s, &c);
            float sp, cp, sm, cm;
            __sincosf(-0.5f * (phi + omega), &sp, &cp);   // ep = exp(-i(phi+omega)/2)
            __sincosf( 0.5f * (phi - omega), &sm, &cm);   // em = exp( i(phi-omega)/2)
            Cx ep = { cp, sp }, em = { cm, sm };
            r[w][0][0] = { ep.re * c, ep.im * c };
            r[w][0][1] = { -em.re * s, -em.im * s };
            r[w][1][0] = { em.re * s, -em.im * s };       // conj(em)*s
            r[w][1][1] = { ep.re * c, -ep.im * c };       // conj(ep)*c
        }
        // G = kron(r0, r1)
        Cx G[4][4];
        #pragma unroll
        for (int a = 0; a < 2; a++)
            for (int b = 0; b < 2; b++)
                for (int c2 = 0; c2 < 2; c2++)
                    for (int d = 0; d < 2; d++)
                        G[2 * a + b][2 * c2 + d] = cmul(r[0][a][c2], r[1][b][d]);
        // T = G @ U
        Cx T[4][4];
        #pragma unroll
        for (int i = 0; i < 4; i++)
            for (int j = 0; j < 4; j++) {
                Cx acc = { 0.f, 0.f };
                for (int k = 0; k < 4; k++) acc = cadd(acc, cmul(G[i][k], U[k][j]));
                T[i][j] = acc;
            }
        // CNOT01 (swap rows 2,3) then CNOT10 (swap rows 1,3 of the result)
        // net row permutation of T: new = (T0, T2, T3, T1)
        for (int j = 0; j < 4; j++) {
            U[0][j] = T[0][j];
            U[1][j] = T[2][j];
            U[2][j] = T[3][j];
            U[3][j] = T[1][j];
        }
    }

    // A[i][j] = fc_w * Re( sum_k z_k conj(U[k][i]) U[k][j] ),  z = (1,1,-1,-1)
    float wgt = fc_w[0];
    float A[4][4];
    #pragma unroll
    for (int i = 0; i < 4; i++)
        for (int j = 0; j < 4; j++) {
            float acc = 0.f;
            for (int k = 0; k < 4; k++) {
                float zk = (k < 2) ? 1.f : -1.f;
                acc += zk * (U[k][i].re * U[k][j].re + U[k][i].im * U[k][j].im);
            }
            A[i][j] = wgt * acc;
        }

    // Fold half-angle products into full-angle bilinear form:
    // ev = k00 + k01*C1 + k02*S1 + C0*(k10 + k11*C1 + k12*S1) + S0*(k20 + k21*C1 + k22*S1)
    g_K[0] = 0.25f * (A[0][0] + A[1][1] + A[2][2] + A[3][3]) + fc_b[0];
    g_K[1] = 0.25f * (A[0][0] - A[1][1] + A[2][2] - A[3][3]);   // C1
    g_K[2] = 0.50f * (A[0][1] + A[2][3]);                       // S1
    g_K[3] = 0.25f * (A[0][0] + A[1][1] - A[2][2] - A[3][3]);   // C0
    g_K[4] = 0.25f * (A[0][0] - A[1][1] - A[2][2] + A[3][3]);   // C0C1
    g_K[5] = 0.50f * (A[0][1] - A[2][3]);                       // C0S1
    g_K[6] = 0.50f * (A[0][2] + A[1][3]);                       // S0
    g_K[7] = 0.50f * (A[0][2] - A[1][3]);                       // S0C1
    g_K[8] = 0.50f * (A[0][3] + A[1][2]);                       // S0S1
}

// --- main: streaming, 4 samples per thread ----------------------------------
__global__ void __launch_bounds__(256)
qnn_main_kernel(const float4* __restrict__ x4, float4* __restrict__ out4, int nquad) {
    int t = blockIdx.x * blockDim.x + threadIdx.x;
    if (t >= nquad) return;

    float k00 = g_K[0], k01 = g_K[1], k02 = g_K[2];
    float k10 = g_K[3], k11 = g_K[4], k12 = g_K[5];
    float k20 = g_K[6], k21 = g_K[7], k22 = g_K[8];

    float4 xa = x4[2 * t];
    float4 xb = x4[2 * t + 1];
    float xs[8] = { xa.x, xa.y, xa.z, xa.w, xb.x, xb.y, xb.z, xb.w };

    float res[4];
    #pragma unroll
    for (int s = 0; s < 4; s++) {
        float C0, S0, C1, S1;
        __sincosf(xs[2 * s + 0], &S0, &C0);
        __sincosf(xs[2 * s + 1], &S1, &C1);
        float row1 = k10 + k11 * C1 + k12 * S1;
        float row2 = k20 + k21 * C1 + k22 * S1;
        res[s] = (k00 + k01 * C1 + k02 * S1) + C0 * row1 + S0 * row2;
    }
    out4[t] = make_float4(res[0], res[1], res[2], res[3]);
}

extern "C" void kernel_launch(void* const* d_in, const int* in_sizes, int n_in,
                              void* d_out, int out_size) {
    const float* x    = (const float*)d_in[0];   // [B, 2]
    const float* qp   = (const float*)d_in[1];   // [2, 2, 3]
    const float* fc_w = (const float*)d_in[2];   // [1, 1]
    const float* fc_b = (const float*)d_in[3];   // [1]
    float* out = (float*)d_out;                  // [B, 1]

    qnn_prep_kernel<<<1, 1>>>(qp, fc_w, fc_b);

    int nquad = out_size / 4;                    // 4 samples per thread
    int threads = 256;
    int blocks = (nquad + threads - 1) / threads;
    qnn_main_kernel<<<blocks, threads>>>((const float4*)x, (float4*)d_out, nquad);
    (void)n_in; (void)in_sizes; (void)out;
}